// round 5
// baseline (speedup 1.0000x reference)
#include <cuda_runtime.h>
#include <cuda_bf16.h>
#include <cstdint>
#include <cstring>

typedef unsigned long long u64;

// Scratch: packed float2 h-pairs, layout [sk][b][hp][n]
//   sk = side*8 + k (side0 = HI, side1 = HJ + b1), b 0..7, hp 0..63, n 0..255
__device__ __align__(16) float2 g_H2[16u * 8u * 64u * 256u];   // 16 MB (L2-resident)

// ---------------------------------------------------------------------------
// small PTX helpers
// ---------------------------------------------------------------------------
static __device__ __forceinline__ void cpa16(void* dst, const void* src) {
    uint32_t d = (uint32_t)__cvta_generic_to_shared(dst);
    asm volatile("cp.async.cg.shared.global [%0], [%1], 16;" :: "r"(d), "l"(src));
}
static __device__ __forceinline__ void cpa_commit() {
    asm volatile("cp.async.commit_group;");
}
template<int N> static __device__ __forceinline__ void cpa_wait() {
    asm volatile("cp.async.wait_group %0;" :: "n"(N));
}
static __device__ __forceinline__ void f2_unpack(u64 v, float& lo, float& hi) {
    asm("mov.b64 {%0, %1}, %2;" : "=f"(lo), "=f"(hi) : "l"(v));
}
// acc += relu(hs + hj) * wp   (per f32 lane), one asm block so ptxas can
// register-rename the mov.b64 pairs instead of emitting MOVs.
static __device__ __forceinline__ void relu_dot(u64& acc, u64 hs, u64 hj, u64 wp) {
    asm("{\n\t"
        ".reg .f32 lo, hi;\n\t"
        ".reg .b64 s;\n\t"
        "add.rn.f32x2 s, %1, %2;\n\t"
        "mov.b64 {lo, hi}, s;\n\t"
        "max.f32 lo, lo, 0f00000000;\n\t"
        "max.f32 hi, hi, 0f00000000;\n\t"
        "mov.b64 s, {lo, hi};\n\t"
        "fma.rn.f32x2 %0, s, %3, %0;\n\t"
        "}" : "+l"(acc) : "l"(hs), "l"(hj), "l"(wp));
}

// ---------------------------------------------------------------------------
// Kernel 1: HI / HJB = E @ W1_slice (+ b1 for side 1).
// 16 GEMMs 2048m x 128h x 128d fp32, f32x2 packed over h-pairs.
// Double-buffered: B via cp.async, A via register prefetch + duplicated store.
// ---------------------------------------------------------------------------
__global__ void __launch_bounds__(256, 2)
k1_gemm(const float* __restrict__ E, const float* __restrict__ W1,
        const float* __restrict__ b1)
{
    __shared__ __align__(16) float2 aS[2][16][128];  // [buf][d][m] = (a,a) dup, 32KB
    __shared__ __align__(16) float  bS[2][16][128];  // [buf][d][h] plain,      16KB

    const int t     = threadIdx.x;
    const int mtile = blockIdx.x;          // 0..15
    const int sk    = blockIdx.y;          // 0..15
    const int k     = sk & 7;
    const int side  = sk >> 3;
    const float* Wb = W1 + (size_t)k * 32768 + (size_t)side * 16384; // [d][h]

    const int tn = t & 15, tm = t >> 4;        // compute mapping
    const int arow = t >> 2, adq = t & 3;      // A loader
    const int bd = t >> 5, bq = t & 31;        // B cp.async loader (first half)
    const int bd2 = bd + 8;

    u64 acc[8][4];
    #pragma unroll
    for (int v = 0; v < 8; ++v)
        #pragma unroll
        for (int u = 0; u < 4; ++u) acc[v][u] = 0ULL;

    // --- prologue ---
    float4 rA0, rA1;
    // chunk 0 A -> regs -> smem[0]
    rA0 = *(const float4*)(E + (size_t)(mtile * 128 + arow) * 128 + 0 + adq * 4);
    rA1 = *(const float4*)(E + (size_t)(mtile * 128 + arow + 64) * 128 + 0 + adq * 4);
    {
        float x[4] = {rA0.x, rA0.y, rA0.z, rA0.w};
        float y[4] = {rA1.x, rA1.y, rA1.z, rA1.w};
        #pragma unroll
        for (int q = 0; q < 4; ++q) {
            aS[0][adq * 4 + q][arow]      = make_float2(x[q], x[q]);
            aS[0][adq * 4 + q][arow + 64] = make_float2(y[q], y[q]);
        }
    }
    // chunk 1 A -> regs
    rA0 = *(const float4*)(E + (size_t)(mtile * 128 + arow) * 128 + 16 + adq * 4);
    rA1 = *(const float4*)(E + (size_t)(mtile * 128 + arow + 64) * 128 + 16 + adq * 4);
    // chunk 0,1 B -> cp.async
    #pragma unroll
    for (int c = 0; c < 2; ++c) {
        cpa16(&bS[c][bd][bq * 4],  Wb + (size_t)(c * 16 + bd)  * 128 + bq * 4);
        cpa16(&bS[c][bd2][bq * 4], Wb + (size_t)(c * 16 + bd2) * 128 + bq * 4);
        cpa_commit();
    }

    #pragma unroll
    for (int c = 0; c < 8; ++c) {
        if (c < 7) cpa_wait<1>(); else cpa_wait<0>();
        __syncthreads();
        // stage A(c+1) from regs into the other buffer
        if (c + 1 < 8) {
            float x[4] = {rA0.x, rA0.y, rA0.z, rA0.w};
            float y[4] = {rA1.x, rA1.y, rA1.z, rA1.w};
            int nb = (c + 1) & 1;
            #pragma unroll
            for (int q = 0; q < 4; ++q) {
                aS[nb][adq * 4 + q][arow]      = make_float2(x[q], x[q]);
                aS[nb][adq * 4 + q][arow + 64] = make_float2(y[q], y[q]);
            }
        }
        // compute chunk c
        const int buf = c & 1;
        #pragma unroll
        for (int d = 0; d < 16; ++d) {
            u64 b2r[4];
            #pragma unroll
            for (int u = 0; u < 4; ++u)
                b2r[u] = *(const u64*)&bS[buf][d][2 * (tn + 16 * u)];
            #pragma unroll
            for (int v = 0; v < 8; ++v) {
                u64 ad = *(const u64*)&aS[buf][d][tm * 8 + v];
                #pragma unroll
                for (int u = 0; u < 4; ++u)
                    asm("fma.rn.f32x2 %0, %1, %2, %0;"
                        : "+l"(acc[v][u]) : "l"(ad), "l"(b2r[u]));
            }
        }
        __syncthreads();
        // prefetch chunk c+2
        if (c + 2 < 8) {
            int d0 = (c + 2) * 16;
            rA0 = *(const float4*)(E + (size_t)(mtile * 128 + arow) * 128 + d0 + adq * 4);
            rA1 = *(const float4*)(E + (size_t)(mtile * 128 + arow + 64) * 128 + d0 + adq * 4);
            cpa16(&bS[buf][bd][bq * 4],  Wb + (size_t)(d0 + bd)  * 128 + bq * 4);
            cpa16(&bS[buf][bd2][bq * 4], Wb + (size_t)(d0 + bd2) * 128 + bq * 4);
            cpa_commit();
        }
    }

    // epilogue: add b1 pair (side 1), store transposed [sk][b][hp][n]
    const int b     = mtile >> 1;
    const int nbase = (mtile & 1) * 128 + tm * 8;
    const float* b1k = b1 + k * 128;
    #pragma unroll
    for (int u = 0; u < 4; ++u) {
        int hp = tn + 16 * u;
        float bx = 0.0f, by = 0.0f;
        if (side) { bx = b1k[2 * hp]; by = b1k[2 * hp + 1]; }
        size_t rowbase = ((size_t)(sk * 8 + b) * 64 + hp) * 256;
        #pragma unroll
        for (int v = 0; v < 8; ++v) {
            float lo, hi; f2_unpack(acc[v][u], lo, hi);
            g_H2[rowbase + nbase + v] = make_float2(lo + bx, hi + by);
        }
    }
}

// ---------------------------------------------------------------------------
// Kernel 2: pair loop + entmax-1.5 closed form.
// Block: one (b,k), 64i x 128j tile, 256 threads, 4i x 8j per thread.
// 8 chunks of 8 h-pairs, cp.async double-buffered from L2-resident g_H2.
// ---------------------------------------------------------------------------
__global__ void __launch_bounds__(256, 2)
k2_pairs(const float* __restrict__ W2, const float* __restrict__ b2,
         const float* __restrict__ W3, const float* __restrict__ b3,
         float* __restrict__ out)
{
    __shared__ __align__(16) float2 hiS[2][8][64];    // 8KB
    __shared__ __align__(16) float2 hjS[2][8][128];   // 16KB
    __shared__ float2 w2S[64];

    const int t  = threadIdx.x;
    const int z  = blockIdx.z;
    const int b  = z >> 3, k = z & 7;
    const int i0 = blockIdx.y * 64;
    const int j0 = blockIdx.x * 128;

    if (t < 64) {
        const float* w2k = W2 + k * 256;   // [h][c]
        w2S[t] = make_float2(0.25f * (w2k[4 * t + 0] - w2k[4 * t + 1]),
                             0.25f * (w2k[4 * t + 2] - w2k[4 * t + 3]));
    }

    const int tj = t & 15, ti = t >> 4;

    const float2* hib = g_H2 + ((size_t)(k * 8 + b) * 64) * 256 + i0;        // side 0
    const float2* hjb = g_H2 + ((size_t)((8 + k) * 8 + b) * 64) * 256 + j0;  // side 1

    // loader mappings (16B = 2 float2 per cp.async)
    const int hip = t >> 5, hiq = t & 31;          // hi: 1 op/thread
    const int hjp0 = t >> 6, hjq0 = t & 63;        // hj: 2 ops/thread
    const int hjp1 = (t + 256) >> 6, hjq1 = t & 63;

    u64 acc[4][8];
    #pragma unroll
    for (int a = 0; a < 4; ++a)
        #pragma unroll
        for (int cc = 0; cc < 8; ++cc) acc[a][cc] = 0ULL;

    // prologue: chunks 0,1 in flight
    #pragma unroll
    for (int c = 0; c < 2; ++c) {
        int hp0 = c * 8;
        cpa16(&hiS[c][hip][hiq * 2],  hib + (size_t)(hp0 + hip) * 256 + hiq * 2);
        cpa16(&hjS[c][hjp0][hjq0 * 2], hjb + (size_t)(hp0 + hjp0) * 256 + hjq0 * 2);
        cpa16(&hjS[c][hjp1][hjq1 * 2], hjb + (size_t)(hp0 + hjp1) * 256 + hjq1 * 2);
        cpa_commit();
    }

    #pragma unroll
    for (int c = 0; c < 8; ++c) {
        if (c < 7) cpa_wait<1>(); else cpa_wait<0>();
        __syncthreads();
        const int buf = c & 1;
        #pragma unroll
        for (int p = 0; p < 8; ++p) {
            u64 wp = *(const u64*)&w2S[c * 8 + p];
            ulonglong2 h01 = *(const ulonglong2*)&hiS[buf][p][ti * 4];
            ulonglong2 h23 = *(const ulonglong2*)&hiS[buf][p][ti * 4 + 2];
            u64 hiv[4] = {h01.x, h01.y, h23.x, h23.y};
            #pragma unroll
            for (int cc = 0; cc < 8; ++cc) {
                u64 hj = *(const u64*)&hjS[buf][p][tj + 16 * cc];
                #pragma unroll
                for (int a = 0; a < 4; ++a)
                    relu_dot(acc[a][cc], hiv[a], hj, wp);
            }
        }
        __syncthreads();
        if (c + 2 < 8) {
            int hp0 = (c + 2) * 8;
            cpa16(&hiS[buf][hip][hiq * 2],  hib + (size_t)(hp0 + hip) * 256 + hiq * 2);
            cpa16(&hjS[buf][hjp0][hjq0 * 2], hjb + (size_t)(hp0 + hjp0) * 256 + hjq0 * 2);
            cpa16(&hjS[buf][hjp1][hjq1 * 2], hjb + (size_t)(hp0 + hjp1) * 256 + hjq1 * 2);
            cpa_commit();
        }
    }

    // entmax-1.5 pair closed form + affine output + zero diagonal
    const float tb   = 0.25f * (b2[2 * k] - b2[2 * k + 1]);
    const float w30  = W3[2 * k], w31 = W3[2 * k + 1];
    const float base = w31 + b3[k];
    const float dw3  = w30 - w31;
    const size_t outb = (size_t)(b * 8 + k) * 65536;

    #pragma unroll
    for (int a = 0; a < 4; ++a) {
        int gi = i0 + ti * 4 + a;
        #pragma unroll
        for (int cc = 0; cc < 8; ++cc) {
            int gj = j0 + tj + 16 * cc;
            float lo, hi; f2_unpack(acc[a][cc], lo, hi);
            float tv   = lo + hi + tb;
            float dabs = fabsf(tv);
            float s    = sqrtf(fmaxf(0.5f - dabs * dabs, 0.0f));
            float q    = s + tv;
            float p0   = (dabs >= 0.5f) ? (tv > 0.0f ? 1.0f : 0.0f) : q * q;
            float res  = base + dw3 * p0;
            if (gi == gj) res = 0.0f;
            out[outb + (size_t)gi * 256 + gj] = res;
        }
    }
}

extern "C" void kernel_launch(void* const* d_in, const int* in_sizes, int n_in,
                              void* d_out, int out_size) {
    const float* E  = (const float*)d_in[0];   // (8, 256, 128)
    const float* W1 = (const float*)d_in[1];   // (8, 256, 128)
    const float* b1 = (const float*)d_in[2];   // (8, 128)
    const float* W2 = (const float*)d_in[3];   // (8, 128, 2)
    const float* b2 = (const float*)d_in[4];   // (8, 2)
    const float* W3 = (const float*)d_in[5];   // (8, 2, 1)
    const float* b3 = (const float*)d_in[6];   // (8, 1)
    float* out = (float*)d_out;                // (8, 8, 256, 256)

    k1_gemm<<<dim3(16, 16), 256>>>(E, W1, b1);
    k2_pairs<<<dim3(2, 4, 64), 256>>>(W2, b2, W3, b3, out);
}

// round 8
// speedup vs baseline: 1.0046x; 1.0046x over previous
#include <cuda_runtime.h>
#include <cuda_bf16.h>
#include <cstdint>
#include <cstring>

typedef unsigned long long u64;

// Scratch: packed float2 h-pairs, layout [sk][b][hp][n]
//   sk = side*8 + k (side0 = HI, side1 = HJ + b1), b 0..7, hp 0..63, n 0..255
__device__ __align__(16) float2 g_H2[16u * 8u * 64u * 256u];   // 16 MB (L2-resident)

// ---------------------------------------------------------------------------
// helpers
// ---------------------------------------------------------------------------
static __device__ __forceinline__ void cpa16(void* dst, const void* src) {
    uint32_t d = (uint32_t)__cvta_generic_to_shared(dst);
    asm volatile("cp.async.cg.shared.global [%0], [%1], 16;" :: "r"(d), "l"(src));
}
static __device__ __forceinline__ void cpa_commit() {
    asm volatile("cp.async.commit_group;");
}
template<int N> static __device__ __forceinline__ void cpa_wait() {
    asm volatile("cp.async.wait_group %0;" :: "n"(N));
}
static __device__ __forceinline__ void f2_unpack(u64 v, float& lo, float& hi) {
    asm("mov.b64 {%0, %1}, %2;" : "=f"(lo), "=f"(hi) : "l"(v));
}
// acc += relu(hs + hj) * wp  per f32 lane; single asm block so ptxas can
// register-rename the pack/unpack movs.
static __device__ __forceinline__ void relu_dot(u64& acc, u64 hs, u64 hj, u64 wp) {
    asm("{\n\t"
        ".reg .f32 lo, hi;\n\t"
        ".reg .b64 s;\n\t"
        "add.rn.f32x2 s, %1, %2;\n\t"
        "mov.b64 {lo, hi}, s;\n\t"
        "max.f32 lo, lo, 0f00000000;\n\t"
        "max.f32 hi, hi, 0f00000000;\n\t"
        "mov.b64 s, {lo, hi};\n\t"
        "fma.rn.f32x2 %0, s, %3, %0;\n\t"
        "}" : "+l"(acc) : "l"(hs), "l"(hj), "l"(wp));
}

// ---------------------------------------------------------------------------
// Kernel 1: HI / HJB = E @ W1_slice (+ b1 for side 1).
// 16 GEMMs 2048m x 128h x 128d fp32, f32x2 packed over h-pairs.
// Single-barrier double-buffered pipeline: B via cp.async, A via register
// prefetch + duplicated (a,a) store into smem. Static smem = 48KB exactly.
// ---------------------------------------------------------------------------
__global__ void __launch_bounds__(256, 2)
k1_gemm(const float* __restrict__ E, const float* __restrict__ W1,
        const float* __restrict__ b1)
{
    __shared__ __align__(16) float2 aS[2][16][128];  // [buf][d][m] dup, 32KB
    __shared__ __align__(16) float  bS[2][16][128];  // [buf][d][h],      16KB

    const int t     = threadIdx.x;
    const int mtile = blockIdx.x;          // 0..15
    const int sk    = blockIdx.y;          // 0..15
    const int k     = sk & 7;
    const int side  = sk >> 3;
    const float* Wb = W1 + (size_t)k * 32768 + (size_t)side * 16384; // [d][h]

    const int tn = t & 15, tm = t >> 4;        // compute mapping
    const int arow = t >> 2, adq = t & 3;      // A loader
    const int bd = t >> 5, bq = t & 31;        // B loader
    const int bd2 = bd + 8;

    u64 acc[8][4];
    #pragma unroll
    for (int v = 0; v < 8; ++v)
        #pragma unroll
        for (int u = 0; u < 4; ++u) acc[v][u] = 0ULL;

    const float* Erow0 = E + (size_t)(mtile * 128 + arow) * 128 + adq * 4;
    const float* Erow1 = E + (size_t)(mtile * 128 + arow + 64) * 128 + adq * 4;

    // --- prologue ---
    float4 rA0 = *(const float4*)(Erow0);
    float4 rA1 = *(const float4*)(Erow1);
    {   // stage A(0) into buf 0
        float x[4] = {rA0.x, rA0.y, rA0.z, rA0.w};
        float y[4] = {rA1.x, rA1.y, rA1.z, rA1.w};
        #pragma unroll
        for (int q = 0; q < 4; ++q) {
            aS[0][adq * 4 + q][arow]      = make_float2(x[q], x[q]);
            aS[0][adq * 4 + q][arow + 64] = make_float2(y[q], y[q]);
        }
    }
    cpa16(&bS[0][bd][bq * 4],  Wb + (size_t)bd  * 128 + bq * 4);
    cpa16(&bS[0][bd2][bq * 4], Wb + (size_t)bd2 * 128 + bq * 4);
    cpa_commit();
    // A(1) into regs
    rA0 = *(const float4*)(Erow0 + 16);
    rA1 = *(const float4*)(Erow1 + 16);

    #pragma unroll
    for (int c = 0; c < 8; ++c) {
        cpa_wait<0>();
        __syncthreads();   // data(c) landed AND everyone done with buf (c+1)&1
        if (c < 7) {
            // stage A(c+1) into the other buffer, launch B(c+1)
            const int nb = (c + 1) & 1;
            float x[4] = {rA0.x, rA0.y, rA0.z, rA0.w};
            float y[4] = {rA1.x, rA1.y, rA1.z, rA1.w};
            #pragma unroll
            for (int q = 0; q < 4; ++q) {
                aS[nb][adq * 4 + q][arow]      = make_float2(x[q], x[q]);
                aS[nb][adq * 4 + q][arow + 64] = make_float2(y[q], y[q]);
            }
            const int d0n = (c + 1) * 16;
            cpa16(&bS[nb][bd][bq * 4],  Wb + (size_t)(d0n + bd)  * 128 + bq * 4);
            cpa16(&bS[nb][bd2][bq * 4], Wb + (size_t)(d0n + bd2) * 128 + bq * 4);
            cpa_commit();
        }
        if (c < 6) {       // A(c+2) into regs; latency hidden by compute(c)
            rA0 = *(const float4*)(Erow0 + (c + 2) * 16);
            rA1 = *(const float4*)(Erow1 + (c + 2) * 16);
        }
        // compute chunk c
        const int buf = c & 1;
        #pragma unroll
        for (int d = 0; d < 16; ++d) {
            u64 b2r[4];
            #pragma unroll
            for (int u = 0; u < 4; ++u)
                b2r[u] = *(const u64*)&bS[buf][d][2 * (tn + 16 * u)];
            #pragma unroll
            for (int v = 0; v < 8; ++v) {
                u64 ad = *(const u64*)&aS[buf][d][tm * 8 + v];
                #pragma unroll
                for (int u = 0; u < 4; ++u)
                    asm("fma.rn.f32x2 %0, %1, %2, %0;"
                        : "+l"(acc[v][u]) : "l"(ad), "l"(b2r[u]));
            }
        }
    }

    // epilogue: add b1 pair (side 1), store transposed [sk][b][hp][n]
    const int b     = mtile >> 1;
    const int nbase = (mtile & 1) * 128 + tm * 8;
    const float* b1k = b1 + k * 128;
    #pragma unroll
    for (int u = 0; u < 4; ++u) {
        int hp = tn + 16 * u;
        float bx = 0.0f, by = 0.0f;
        if (side) { bx = b1k[2 * hp]; by = b1k[2 * hp + 1]; }
        size_t rowbase = ((size_t)(sk * 8 + b) * 64 + hp) * 256;
        #pragma unroll
        for (int v = 0; v < 8; ++v) {
            float lo, hi; f2_unpack(acc[v][u], lo, hi);
            g_H2[rowbase + nbase + v] = make_float2(lo + bx, hi + by);
        }
    }
}

// ---------------------------------------------------------------------------
// Kernel 2: pair loop + entmax-1.5 closed form.
// Block: one (b,k), 64i x 128j tile, 256 threads, 4i x 8j per thread.
// 4 chunks of 16 h-pairs; single-barrier double-buffered cp.async pipeline
// (4 __syncthreads per block total). DYNAMIC smem (49.7KB > 48KB static cap).
// Layout in dynamic smem:
//   hiS: float2 [2][16][64]   at byte      0  (16384 B)
//   hjS: float2 [2][16][128]  at byte  16384  (32768 B)
//   w2S: float2 [64]          at byte  49152  (  512 B)
// ---------------------------------------------------------------------------
#define K2_SMEM_BYTES (16384 + 32768 + 512)

__global__ void __launch_bounds__(256, 2)
k2_pairs(const float* __restrict__ W2, const float* __restrict__ b2,
         const float* __restrict__ W3, const float* __restrict__ b3,
         float* __restrict__ out)
{
    extern __shared__ __align__(16) char smem[];
    float2 (*hiS)[16][64]  = (float2(*)[16][64])(smem);
    float2 (*hjS)[16][128] = (float2(*)[16][128])(smem + 16384);
    float2* w2S            = (float2*)(smem + 49152);

    const int t  = threadIdx.x;
    const int z  = blockIdx.z;
    const int b  = z >> 3, k = z & 7;
    const int i0 = blockIdx.y * 64;
    const int j0 = blockIdx.x * 128;

    if (t < 64) {
        const float* w2k = W2 + k * 256;   // [h][c]
        w2S[t] = make_float2(0.25f * (w2k[4 * t + 0] - w2k[4 * t + 1]),
                             0.25f * (w2k[4 * t + 2] - w2k[4 * t + 3]));
    }

    const int tj = t & 15, ti = t >> 4;

    const float2* hib = g_H2 + ((size_t)(k * 8 + b) * 64) * 256 + i0;        // side 0
    const float2* hjb = g_H2 + ((size_t)((8 + k) * 8 + b) * 64) * 256 + j0;  // side 1

    u64 acc[4][8];
    #pragma unroll
    for (int a = 0; a < 4; ++a)
        #pragma unroll
        for (int cc = 0; cc < 8; ++cc) acc[a][cc] = 0ULL;

    // chunk loader: hi = 16hp x 64i (8KB, 2 ops/thread), hj = 16hp x 128j (16KB, 4 ops/thread)
    #define K2_PREFETCH(chunk, bufn) do {                                          \
        const int _hp0 = (chunk) * 16;                                             \
        _Pragma("unroll")                                                          \
        for (int r = 0; r < 2; ++r) {                                              \
            int o = t + 256 * r, p = o >> 5, q = o & 31;                           \
            cpa16(&hiS[bufn][p][q * 2], hib + (size_t)(_hp0 + p) * 256 + q * 2);   \
        }                                                                          \
        _Pragma("unroll")                                                          \
        for (int r = 0; r < 4; ++r) {                                              \
            int o = t + 256 * r, p = o >> 6, q = o & 63;                           \
            cpa16(&hjS[bufn][p][q * 2], hjb + (size_t)(_hp0 + p) * 256 + q * 2);   \
        }                                                                          \
        cpa_commit();                                                              \
    } while (0)

    K2_PREFETCH(0, 0);

    #pragma unroll
    for (int c = 0; c < 4; ++c) {
        cpa_wait<0>();
        __syncthreads();   // data(c) landed AND all threads done with buf (c+1)&1
        if (c < 3) K2_PREFETCH(c + 1, (c + 1) & 1);
        const int buf = c & 1;
        #pragma unroll 8
        for (int p = 0; p < 16; ++p) {
            u64 wp = *(const u64*)&w2S[c * 16 + p];
            ulonglong2 h01 = *(const ulonglong2*)&hiS[buf][p][ti * 4];
            ulonglong2 h23 = *(const ulonglong2*)&hiS[buf][p][ti * 4 + 2];
            u64 hiv[4] = {h01.x, h01.y, h23.x, h23.y};
            #pragma unroll
            for (int cc = 0; cc < 8; ++cc) {
                u64 hj = *(const u64*)&hjS[buf][p][tj + 16 * cc];
                #pragma unroll
                for (int a = 0; a < 4; ++a)
                    relu_dot(acc[a][cc], hiv[a], hj, wp);
            }
        }
    }
    #undef K2_PREFETCH

    // entmax-1.5 pair closed form + affine output + zero diagonal
    const float tb   = 0.25f * (b2[2 * k] - b2[2 * k + 1]);
    const float w30  = W3[2 * k], w31 = W3[2 * k + 1];
    const float base = w31 + b3[k];
    const float dw3  = w30 - w31;
    const size_t outb = (size_t)(b * 8 + k) * 65536;

    #pragma unroll
    for (int a = 0; a < 4; ++a) {
        int gi = i0 + ti * 4 + a;
        #pragma unroll
        for (int cc = 0; cc < 8; ++cc) {
            int gj = j0 + tj + 16 * cc;
            float lo, hi; f2_unpack(acc[a][cc], lo, hi);
            float tv   = lo + hi + tb;
            float dabs = fabsf(tv);
            float s    = sqrtf(fmaxf(0.5f - dabs * dabs, 0.0f));
            float q    = s + tv;
            float p0   = (dabs >= 0.5f) ? (tv > 0.0f ? 1.0f : 0.0f) : q * q;
            float res  = base + dw3 * p0;
            if (gi == gj) res = 0.0f;
            out[outb + (size_t)gi * 256 + gj] = res;
        }
    }
}

extern "C" void kernel_launch(void* const* d_in, const int* in_sizes, int n_in,
                              void* d_out, int out_size) {
    const float* E  = (const float*)d_in[0];   // (8, 256, 128)
    const float* W1 = (const float*)d_in[1];   // (8, 256, 128)
    const float* b1 = (const float*)d_in[2];   // (8, 128)
    const float* W2 = (const float*)d_in[3];   // (8, 128, 2)
    const float* b2 = (const float*)d_in[4];   // (8, 2)
    const float* W3 = (const float*)d_in[5];   // (8, 2, 1)
    const float* b3 = (const float*)d_in[6];   // (8, 1)
    float* out = (float*)d_out;                // (8, 8, 256, 256)

    // Raise dynamic-smem cap for k2 (49.7KB > default 48KB). Non-stream API:
    // executes immediately, safe under graph capture, no allocation.
    cudaFuncSetAttribute(k2_pairs, cudaFuncAttributeMaxDynamicSharedMemorySize,
                         K2_SMEM_BYTES);

    k1_gemm<<<dim3(16, 16), 256>>>(E, W1, b1);
    k2_pairs<<<dim3(2, 4, 64), 256, K2_SMEM_BYTES>>>(W2, b2, W3, b3, out);
}

// round 9
// speedup vs baseline: 1.0901x; 1.0851x over previous
#include <cuda_runtime.h>
#include <cuda_bf16.h>
#include <cstdint>
#include <cstring>

typedef unsigned long long u64;

// Scratch: packed float2 h-pairs, layout [sk][b][hp][n]
//   sk = side*8 + k (side0 = HI, side1 = HJ + b1), b 0..7, hp 0..63, n 0..255
__device__ __align__(16) float2 g_H2[16u * 8u * 64u * 256u];   // 16 MB (L2-resident)

// ---------------------------------------------------------------------------
// helpers
// ---------------------------------------------------------------------------
static __device__ __forceinline__ void cpa16(void* dst, const void* src) {
    uint32_t d = (uint32_t)__cvta_generic_to_shared(dst);
    asm volatile("cp.async.cg.shared.global [%0], [%1], 16;" :: "r"(d), "l"(src));
}
static __device__ __forceinline__ void cpa_commit() {
    asm volatile("cp.async.commit_group;");
}
template<int N> static __device__ __forceinline__ void cpa_wait() {
    asm volatile("cp.async.wait_group %0;" :: "n"(N));
}
static __device__ __forceinline__ void f2_unpack(u64 v, float& lo, float& hi) {
    asm("mov.b64 {%0, %1}, %2;" : "=f"(lo), "=f"(hi) : "l"(v));
}
// acc += relu(hs + hj) * wp  per f32 lane; single asm block so ptxas can
// register-rename the pack/unpack movs.
static __device__ __forceinline__ void relu_dot(u64& acc, u64 hs, u64 hj, u64 wp) {
    asm("{\n\t"
        ".reg .f32 lo, hi;\n\t"
        ".reg .b64 s;\n\t"
        "add.rn.f32x2 s, %1, %2;\n\t"
        "mov.b64 {lo, hi}, s;\n\t"
        "max.f32 lo, lo, 0f00000000;\n\t"
        "max.f32 hi, hi, 0f00000000;\n\t"
        "mov.b64 s, {lo, hi};\n\t"
        "fma.rn.f32x2 %0, s, %3, %0;\n\t"
        "}" : "+l"(acc) : "l"(hs), "l"(hj), "l"(wp));
}

// ---------------------------------------------------------------------------
// Kernel 1: HI / HJB = E @ W1_slice (+ b1 for side 1).
// EXACT revert to the R5 version measured at ~12.4us: depth-2 cp.async
// pipeline (wait<1>), two __syncthreads per chunk. Static smem = 48KB.
// ---------------------------------------------------------------------------
__global__ void __launch_bounds__(256, 2)
k1_gemm(const float* __restrict__ E, const float* __restrict__ W1,
        const float* __restrict__ b1)
{
    __shared__ __align__(16) float2 aS[2][16][128];  // [buf][d][m] dup, 32KB
    __shared__ __align__(16) float  bS[2][16][128];  // [buf][d][h],      16KB

    const int t     = threadIdx.x;
    const int mtile = blockIdx.x;          // 0..15
    const int sk    = blockIdx.y;          // 0..15
    const int k     = sk & 7;
    const int side  = sk >> 3;
    const float* Wb = W1 + (size_t)k * 32768 + (size_t)side * 16384; // [d][h]

    const int tn = t & 15, tm = t >> 4;        // compute mapping
    const int arow = t >> 2, adq = t & 3;      // A loader
    const int bd = t >> 5, bq = t & 31;        // B loader
    const int bd2 = bd + 8;

    u64 acc[8][4];
    #pragma unroll
    for (int v = 0; v < 8; ++v)
        #pragma unroll
        for (int u = 0; u < 4; ++u) acc[v][u] = 0ULL;

    // --- prologue ---
    float4 rA0, rA1;
    // chunk 0 A -> regs -> smem[0]
    rA0 = *(const float4*)(E + (size_t)(mtile * 128 + arow) * 128 + 0 + adq * 4);
    rA1 = *(const float4*)(E + (size_t)(mtile * 128 + arow + 64) * 128 + 0 + adq * 4);
    {
        float x[4] = {rA0.x, rA0.y, rA0.z, rA0.w};
        float y[4] = {rA1.x, rA1.y, rA1.z, rA1.w};
        #pragma unroll
        for (int q = 0; q < 4; ++q) {
            aS[0][adq * 4 + q][arow]      = make_float2(x[q], x[q]);
            aS[0][adq * 4 + q][arow + 64] = make_float2(y[q], y[q]);
        }
    }
    // chunk 1 A -> regs
    rA0 = *(const float4*)(E + (size_t)(mtile * 128 + arow) * 128 + 16 + adq * 4);
    rA1 = *(const float4*)(E + (size_t)(mtile * 128 + arow + 64) * 128 + 16 + adq * 4);
    // chunk 0,1 B -> cp.async (two groups in flight)
    #pragma unroll
    for (int c = 0; c < 2; ++c) {
        cpa16(&bS[c][bd][bq * 4],  Wb + (size_t)(c * 16 + bd)  * 128 + bq * 4);
        cpa16(&bS[c][bd2][bq * 4], Wb + (size_t)(c * 16 + bd2) * 128 + bq * 4);
        cpa_commit();
    }

    #pragma unroll
    for (int c = 0; c < 8; ++c) {
        if (c < 7) cpa_wait<1>(); else cpa_wait<0>();
        __syncthreads();
        // stage A(c+1) from regs into the other buffer
        if (c + 1 < 8) {
            float x[4] = {rA0.x, rA0.y, rA0.z, rA0.w};
            float y[4] = {rA1.x, rA1.y, rA1.z, rA1.w};
            int nb = (c + 1) & 1;
            #pragma unroll
            for (int q = 0; q < 4; ++q) {
                aS[nb][adq * 4 + q][arow]      = make_float2(x[q], x[q]);
                aS[nb][adq * 4 + q][arow + 64] = make_float2(y[q], y[q]);
            }
        }
        // compute chunk c
        const int buf = c & 1;
        #pragma unroll
        for (int d = 0; d < 16; ++d) {
            u64 b2r[4];
            #pragma unroll
            for (int u = 0; u < 4; ++u)
                b2r[u] = *(const u64*)&bS[buf][d][2 * (tn + 16 * u)];
            #pragma unroll
            for (int v = 0; v < 8; ++v) {
                u64 ad = *(const u64*)&aS[buf][d][tm * 8 + v];
                #pragma unroll
                for (int u = 0; u < 4; ++u)
                    asm("fma.rn.f32x2 %0, %1, %2, %0;"
                        : "+l"(acc[v][u]) : "l"(ad), "l"(b2r[u]));
            }
        }
        __syncthreads();
        // prefetch chunk c+2
        if (c + 2 < 8) {
            int d0 = (c + 2) * 16;
            rA0 = *(const float4*)(E + (size_t)(mtile * 128 + arow) * 128 + d0 + adq * 4);
            rA1 = *(const float4*)(E + (size_t)(mtile * 128 + arow + 64) * 128 + d0 + adq * 4);
            cpa16(&bS[buf][bd][bq * 4],  Wb + (size_t)(d0 + bd)  * 128 + bq * 4);
            cpa16(&bS[buf][bd2][bq * 4], Wb + (size_t)(d0 + bd2) * 128 + bq * 4);
            cpa_commit();
        }
    }

    // epilogue: add b1 pair (side 1), store transposed [sk][b][hp][n]
    const int b     = mtile >> 1;
    const int nbase = (mtile & 1) * 128 + tm * 8;
    const float* b1k = b1 + k * 128;
    #pragma unroll
    for (int u = 0; u < 4; ++u) {
        int hp = tn + 16 * u;
        float bx = 0.0f, by = 0.0f;
        if (side) { bx = b1k[2 * hp]; by = b1k[2 * hp + 1]; }
        size_t rowbase = ((size_t)(sk * 8 + b) * 64 + hp) * 256;
        #pragma unroll
        for (int v = 0; v < 8; ++v) {
            float lo, hi; f2_unpack(acc[v][u], lo, hi);
            g_H2[rowbase + nbase + v] = make_float2(lo + bx, hi + by);
        }
    }
}

// ---------------------------------------------------------------------------
// Kernel 2: pair loop + entmax-1.5 closed form.
// NEW: block tile 64i x 64j over ALL 64 h-pairs in one shot.
//   - single cp.async load phase (64KB), ONE __syncthreads per block
//   - per thread 4i x 4j -> 32 accumulator regs (was 64) -> 3 blocks/SM
//   - grid 1024 blocks (~7 waves/SM) hides each block's load prologue
// Dynamic smem layout:
//   hiS: float2 [64][64] at      0  (32768 B)
//   hjS: float2 [64][64] at  32768  (32768 B)
//   w2S: float2 [64]     at  65536  (  512 B)
// ---------------------------------------------------------------------------
#define K2_SMEM_BYTES (32768 + 32768 + 512)

__global__ void __launch_bounds__(256, 3)
k2_pairs(const float* __restrict__ W2, const float* __restrict__ b2,
         const float* __restrict__ W3, const float* __restrict__ b3,
         float* __restrict__ out)
{
    extern __shared__ __align__(16) char smem[];
    float2 (*hiS)[64] = (float2(*)[64])(smem);
    float2 (*hjS)[64] = (float2(*)[64])(smem + 32768);
    float2* w2S       = (float2*)(smem + 65536);

    const int t  = threadIdx.x;
    const int z  = blockIdx.z;
    const int b  = z >> 3, k = z & 7;
    const int i0 = blockIdx.y * 64;
    const int j0 = blockIdx.x * 64;

    if (t < 64) {
        const float* w2k = W2 + k * 256;   // [h][c]
        w2S[t] = make_float2(0.25f * (w2k[4 * t + 0] - w2k[4 * t + 1]),
                             0.25f * (w2k[4 * t + 2] - w2k[4 * t + 3]));
    }

    const float2* hib = g_H2 + ((size_t)(k * 8 + b) * 64) * 256 + i0;        // side 0
    const float2* hjb = g_H2 + ((size_t)((8 + k) * 8 + b) * 64) * 256 + j0;  // side 1

    // load both 64hp x 64 tiles: 8 x 16B per thread per tile
    #pragma unroll
    for (int r = 0; r < 8; ++r) {
        int o = t + 256 * r;
        int p = o >> 5, q = o & 31;          // q in 16B units (2 float2)
        cpa16(&hiS[p][q * 2], hib + (size_t)p * 256 + q * 2);
        cpa16(&hjS[p][q * 2], hjb + (size_t)p * 256 + q * 2);
    }
    cpa_commit();

    u64 acc[4][4];
    #pragma unroll
    for (int a = 0; a < 4; ++a)
        #pragma unroll
        for (int u = 0; u < 4; ++u) acc[a][u] = 0ULL;

    cpa_wait<0>();
    __syncthreads();    // the only barrier in the kernel

    const int tj = t & 15, ti = t >> 4;

    #pragma unroll 4
    for (int p = 0; p < 64; ++p) {
        u64 wp = *(const u64*)&w2S[p];
        ulonglong2 h01 = *(const ulonglong2*)&hiS[p][ti * 4];
        ulonglong2 h23 = *(const ulonglong2*)&hiS[p][ti * 4 + 2];
        u64 hiv[4] = {h01.x, h01.y, h23.x, h23.y};
        #pragma unroll
        for (int u = 0; u < 4; ++u) {
            u64 hj = *(const u64*)&hjS[p][tj + 16 * u];
            #pragma unroll
            for (int a = 0; a < 4; ++a)
                relu_dot(acc[a][u], hiv[a], hj, wp);
        }
    }

    // entmax-1.5 pair closed form + affine output + zero diagonal
    const float tb   = 0.25f * (b2[2 * k] - b2[2 * k + 1]);
    const float w30  = W3[2 * k], w31 = W3[2 * k + 1];
    const float base = w31 + b3[k];
    const float dw3  = w30 - w31;
    const size_t outb = (size_t)(b * 8 + k) * 65536;

    #pragma unroll
    for (int a = 0; a < 4; ++a) {
        int gi = i0 + ti * 4 + a;
        #pragma unroll
        for (int u = 0; u < 4; ++u) {
            int gj = j0 + tj + 16 * u;
            float lo, hi; f2_unpack(acc[a][u], lo, hi);
            float tv   = lo + hi + tb;
            float dabs = fabsf(tv);
            float s    = sqrtf(fmaxf(0.5f - dabs * dabs, 0.0f));
            float q    = s + tv;
            float p0   = (dabs >= 0.5f) ? (tv > 0.0f ? 1.0f : 0.0f) : q * q;
            float res  = base + dw3 * p0;
            if (gi == gj) res = 0.0f;
            out[outb + (size_t)gi * 256 + gj] = res;
        }
    }
}

extern "C" void kernel_launch(void* const* d_in, const int* in_sizes, int n_in,
                              void* d_out, int out_size) {
    const float* E  = (const float*)d_in[0];   // (8, 256, 128)
    const float* W1 = (const float*)d_in[1];   // (8, 256, 128)
    const float* b1 = (const float*)d_in[2];   // (8, 128)
    const float* W2 = (const float*)d_in[3];   // (8, 128, 2)
    const float* b2 = (const float*)d_in[4];   // (8, 2)
    const float* W3 = (const float*)d_in[5];   // (8, 2, 1)
    const float* b3 = (const float*)d_in[6];   // (8, 1)
    float* out = (float*)d_out;                // (8, 8, 256, 256)

    // Raise dynamic-smem cap for k2 (64.5KB). Non-stream API: executes
    // immediately, safe under graph capture, no allocation.
    cudaFuncSetAttribute(k2_pairs, cudaFuncAttributeMaxDynamicSharedMemorySize,
                         K2_SMEM_BYTES);

    k1_gemm<<<dim3(16, 16), 256>>>(E, W1, b1);
    k2_pairs<<<dim3(4, 4, 64), 256, K2_SMEM_BYTES>>>(W2, b2, W3, b3, out);
}

// round 10
// speedup vs baseline: 1.0904x; 1.0003x over previous
#include <cuda_runtime.h>
#include <cuda_bf16.h>
#include <cstdint>
#include <cstring>

typedef unsigned long long u64;

// Scratch: packed float2 h-pairs, layout [sk][b][hp][n]
//   sk = side*8 + k (side0 = HI, side1 = HJ + b1), b 0..7, hp 0..63, n 0..255
__device__ __align__(16) float2 g_H2[16u * 8u * 64u * 256u];   // 16 MB (L2-resident)

// ---------------------------------------------------------------------------
// helpers
// ---------------------------------------------------------------------------
static __device__ __forceinline__ void cpa16(void* dst, const void* src) {
    uint32_t d = (uint32_t)__cvta_generic_to_shared(dst);
    asm volatile("cp.async.cg.shared.global [%0], [%1], 16;" :: "r"(d), "l"(src));
}
static __device__ __forceinline__ void cpa_commit() {
    asm volatile("cp.async.commit_group;");
}
template<int N> static __device__ __forceinline__ void cpa_wait() {
    asm volatile("cp.async.wait_group %0;" :: "n"(N));
}
static __device__ __forceinline__ void f2_unpack(u64 v, float& lo, float& hi) {
    asm("mov.b64 {%0, %1}, %2;" : "=f"(lo), "=f"(hi) : "l"(v));
}
// acc += relu(hs + hj) * wp  per f32 lane; single asm block so ptxas can
// register-rename the pack/unpack movs.
static __device__ __forceinline__ void relu_dot(u64& acc, u64 hs, u64 hj, u64 wp) {
    asm("{\n\t"
        ".reg .f32 lo, hi;\n\t"
        ".reg .b64 s;\n\t"
        "add.rn.f32x2 s, %1, %2;\n\t"
        "mov.b64 {lo, hi}, s;\n\t"
        "max.f32 lo, lo, 0f00000000;\n\t"
        "max.f32 hi, hi, 0f00000000;\n\t"
        "mov.b64 s, {lo, hi};\n\t"
        "fma.rn.f32x2 %0, s, %3, %0;\n\t"
        "}" : "+l"(acc) : "l"(hs), "l"(hj), "l"(wp));
}

// ---------------------------------------------------------------------------
// Kernel 1: HI / HJB = E @ W1_slice (+ b1 for side 1).
// EXACT revert to the R5 version measured at ~12.4us: depth-2 cp.async
// pipeline (wait<1>), two __syncthreads per chunk. Static smem = 48KB.
// ---------------------------------------------------------------------------
__global__ void __launch_bounds__(256, 2)
k1_gemm(const float* __restrict__ E, const float* __restrict__ W1,
        const float* __restrict__ b1)
{
    __shared__ __align__(16) float2 aS[2][16][128];  // [buf][d][m] dup, 32KB
    __shared__ __align__(16) float  bS[2][16][128];  // [buf][d][h],      16KB

    const int t     = threadIdx.x;
    const int mtile = blockIdx.x;          // 0..15
    const int sk    = blockIdx.y;          // 0..15
    const int k     = sk & 7;
    const int side  = sk >> 3;
    const float* Wb = W1 + (size_t)k * 32768 + (size_t)side * 16384; // [d][h]

    const int tn = t & 15, tm = t >> 4;        // compute mapping
    const int arow = t >> 2, adq = t & 3;      // A loader
    const int bd = t >> 5, bq = t & 31;        // B loader
    const int bd2 = bd + 8;

    u64 acc[8][4];
    #pragma unroll
    for (int v = 0; v < 8; ++v)
        #pragma unroll
        for (int u = 0; u < 4; ++u) acc[v][u] = 0ULL;

    // --- prologue ---
    float4 rA0, rA1;
    // chunk 0 A -> regs -> smem[0]
    rA0 = *(const float4*)(E + (size_t)(mtile * 128 + arow) * 128 + 0 + adq * 4);
    rA1 = *(const float4*)(E + (size_t)(mtile * 128 + arow + 64) * 128 + 0 + adq * 4);
    {
        float x[4] = {rA0.x, rA0.y, rA0.z, rA0.w};
        float y[4] = {rA1.x, rA1.y, rA1.z, rA1.w};
        #pragma unroll
        for (int q = 0; q < 4; ++q) {
            aS[0][adq * 4 + q][arow]      = make_float2(x[q], x[q]);
            aS[0][adq * 4 + q][arow + 64] = make_float2(y[q], y[q]);
        }
    }
    // chunk 1 A -> regs
    rA0 = *(const float4*)(E + (size_t)(mtile * 128 + arow) * 128 + 16 + adq * 4);
    rA1 = *(const float4*)(E + (size_t)(mtile * 128 + arow + 64) * 128 + 16 + adq * 4);
    // chunk 0,1 B -> cp.async (two groups in flight)
    #pragma unroll
    for (int c = 0; c < 2; ++c) {
        cpa16(&bS[c][bd][bq * 4],  Wb + (size_t)(c * 16 + bd)  * 128 + bq * 4);
        cpa16(&bS[c][bd2][bq * 4], Wb + (size_t)(c * 16 + bd2) * 128 + bq * 4);
        cpa_commit();
    }

    #pragma unroll
    for (int c = 0; c < 8; ++c) {
        if (c < 7) cpa_wait<1>(); else cpa_wait<0>();
        __syncthreads();
        // stage A(c+1) from regs into the other buffer
        if (c + 1 < 8) {
            float x[4] = {rA0.x, rA0.y, rA0.z, rA0.w};
            float y[4] = {rA1.x, rA1.y, rA1.z, rA1.w};
            int nb = (c + 1) & 1;
            #pragma unroll
            for (int q = 0; q < 4; ++q) {
                aS[nb][adq * 4 + q][arow]      = make_float2(x[q], x[q]);
                aS[nb][adq * 4 + q][arow + 64] = make_float2(y[q], y[q]);
            }
        }
        // compute chunk c
        const int buf = c & 1;
        #pragma unroll
        for (int d = 0; d < 16; ++d) {
            u64 b2r[4];
            #pragma unroll
            for (int u = 0; u < 4; ++u)
                b2r[u] = *(const u64*)&bS[buf][d][2 * (tn + 16 * u)];
            #pragma unroll
            for (int v = 0; v < 8; ++v) {
                u64 ad = *(const u64*)&aS[buf][d][tm * 8 + v];
                #pragma unroll
                for (int u = 0; u < 4; ++u)
                    asm("fma.rn.f32x2 %0, %1, %2, %0;"
                        : "+l"(acc[v][u]) : "l"(ad), "l"(b2r[u]));
            }
        }
        __syncthreads();
        // prefetch chunk c+2
        if (c + 2 < 8) {
            int d0 = (c + 2) * 16;
            rA0 = *(const float4*)(E + (size_t)(mtile * 128 + arow) * 128 + d0 + adq * 4);
            rA1 = *(const float4*)(E + (size_t)(mtile * 128 + arow + 64) * 128 + d0 + adq * 4);
            cpa16(&bS[buf][bd][bq * 4],  Wb + (size_t)(d0 + bd)  * 128 + bq * 4);
            cpa16(&bS[buf][bd2][bq * 4], Wb + (size_t)(d0 + bd2) * 128 + bq * 4);
            cpa_commit();
        }
    }

    // epilogue: add b1 pair (side 1), store transposed [sk][b][hp][n]
    const int b     = mtile >> 1;
    const int nbase = (mtile & 1) * 128 + tm * 8;
    const float* b1k = b1 + k * 128;
    #pragma unroll
    for (int u = 0; u < 4; ++u) {
        int hp = tn + 16 * u;
        float bx = 0.0f, by = 0.0f;
        if (side) { bx = b1k[2 * hp]; by = b1k[2 * hp + 1]; }
        size_t rowbase = ((size_t)(sk * 8 + b) * 64 + hp) * 256;
        #pragma unroll
        for (int v = 0; v < 8; ++v) {
            float lo, hi; f2_unpack(acc[v][u], lo, hi);
            g_H2[rowbase + nbase + v] = make_float2(lo + bx, hi + by);
        }
    }
}

// ---------------------------------------------------------------------------
// Kernel 2: pair loop + entmax-1.5 closed form.
// NEW: block tile 64i x 64j over ALL 64 h-pairs in one shot.
//   - single cp.async load phase (64KB), ONE __syncthreads per block
//   - per thread 4i x 4j -> 32 accumulator regs (was 64) -> 3 blocks/SM
//   - grid 1024 blocks (~7 waves/SM) hides each block's load prologue
// Dynamic smem layout:
//   hiS: float2 [64][64] at      0  (32768 B)
//   hjS: float2 [64][64] at  32768  (32768 B)
//   w2S: float2 [64]     at  65536  (  512 B)
// ---------------------------------------------------------------------------
#define K2_SMEM_BYTES (32768 + 32768 + 512)

__global__ void __launch_bounds__(256, 3)
k2_pairs(const float* __restrict__ W2, const float* __restrict__ b2,
         const float* __restrict__ W3, const float* __restrict__ b3,
         float* __restrict__ out)
{
    extern __shared__ __align__(16) char smem[];
    float2 (*hiS)[64] = (float2(*)[64])(smem);
    float2 (*hjS)[64] = (float2(*)[64])(smem + 32768);
    float2* w2S       = (float2*)(smem + 65536);

    const int t  = threadIdx.x;
    const int z  = blockIdx.z;
    const int b  = z >> 3, k = z & 7;
    const int i0 = blockIdx.y * 64;
    const int j0 = blockIdx.x * 64;

    if (t < 64) {
        const float* w2k = W2 + k * 256;   // [h][c]
        w2S[t] = make_float2(0.25f * (w2k[4 * t + 0] - w2k[4 * t + 1]),
                             0.25f * (w2k[4 * t + 2] - w2k[4 * t + 3]));
    }

    const float2* hib = g_H2 + ((size_t)(k * 8 + b) * 64) * 256 + i0;        // side 0
    const float2* hjb = g_H2 + ((size_t)((8 + k) * 8 + b) * 64) * 256 + j0;  // side 1

    // load both 64hp x 64 tiles: 8 x 16B per thread per tile
    #pragma unroll
    for (int r = 0; r < 8; ++r) {
        int o = t + 256 * r;
        int p = o >> 5, q = o & 31;          // q in 16B units (2 float2)
        cpa16(&hiS[p][q * 2], hib + (size_t)p * 256 + q * 2);
        cpa16(&hjS[p][q * 2], hjb + (size_t)p * 256 + q * 2);
    }
    cpa_commit();

    u64 acc[4][4];
    #pragma unroll
    for (int a = 0; a < 4; ++a)
        #pragma unroll
        for (int u = 0; u < 4; ++u) acc[a][u] = 0ULL;

    cpa_wait<0>();
    __syncthreads();    // the only barrier in the kernel

    const int tj = t & 15, ti = t >> 4;

    #pragma unroll 4
    for (int p = 0; p < 64; ++p) {
        u64 wp = *(const u64*)&w2S[p];
        ulonglong2 h01 = *(const ulonglong2*)&hiS[p][ti * 4];
        ulonglong2 h23 = *(const ulonglong2*)&hiS[p][ti * 4 + 2];
        u64 hiv[4] = {h01.x, h01.y, h23.x, h23.y};
        #pragma unroll
        for (int u = 0; u < 4; ++u) {
            u64 hj = *(const u64*)&hjS[p][tj + 16 * u];
            #pragma unroll
            for (int a = 0; a < 4; ++a)
                relu_dot(acc[a][u], hiv[a], hj, wp);
        }
    }

    // entmax-1.5 pair closed form + affine output + zero diagonal
    const float tb   = 0.25f * (b2[2 * k] - b2[2 * k + 1]);
    const float w30  = W3[2 * k], w31 = W3[2 * k + 1];
    const float base = w31 + b3[k];
    const float dw3  = w30 - w31;
    const size_t outb = (size_t)(b * 8 + k) * 65536;

    #pragma unroll
    for (int a = 0; a < 4; ++a) {
        int gi = i0 + ti * 4 + a;
        #pragma unroll
        for (int u = 0; u < 4; ++u) {
            int gj = j0 + tj + 16 * u;
            float lo, hi; f2_unpack(acc[a][u], lo, hi);
            float tv   = lo + hi + tb;
            float dabs = fabsf(tv);
            float s    = sqrtf(fmaxf(0.5f - dabs * dabs, 0.0f));
            float q    = s + tv;
            float p0   = (dabs >= 0.5f) ? (tv > 0.0f ? 1.0f : 0.0f) : q * q;
            float res  = base + dw3 * p0;
            if (gi == gj) res = 0.0f;
            out[outb + (size_t)gi * 256 + gj] = res;
        }
    }
}

extern "C" void kernel_launch(void* const* d_in, const int* in_sizes, int n_in,
                              void* d_out, int out_size) {
    const float* E  = (const float*)d_in[0];   // (8, 256, 128)
    const float* W1 = (const float*)d_in[1];   // (8, 256, 128)
    const float* b1 = (const float*)d_in[2];   // (8, 128)
    const float* W2 = (const float*)d_in[3];   // (8, 128, 2)
    const float* b2 = (const float*)d_in[4];   // (8, 2)
    const float* W3 = (const float*)d_in[5];   // (8, 2, 1)
    const float* b3 = (const float*)d_in[6];   // (8, 1)
    float* out = (float*)d_out;                // (8, 8, 256, 256)

    // Raise dynamic-smem cap for k2 (64.5KB). Non-stream API: executes
    // immediately, safe under graph capture, no allocation.
    cudaFuncSetAttribute(k2_pairs, cudaFuncAttributeMaxDynamicSharedMemorySize,
                         K2_SMEM_BYTES);

    k1_gemm<<<dim3(16, 16), 256>>>(E, W1, b1);
    k2_pairs<<<dim3(4, 4, 64), 256, K2_SMEM_BYTES>>>(W2, b2, W3, b3, out);
}